// round 14
// baseline (speedup 1.0000x reference)
#include <cuda_runtime.h>
#include <cuda_fp16.h>
#include <cstdint>

#define D_MODEL 1024
#define D_FF    4096
#define N_EXP   8
#define TOPK    2
#define MAX_T   4096
#define MAX_ROWS (MAX_T * TOPK)

// ---------------- scratch (device globals; no allocation allowed) ----------------
__device__ float g_gw[MAX_T * TOPK];
__device__ int   g_geid[MAX_T * TOPK];
__device__ float g_rw[MAX_ROWS];        // compact row -> gate weight
__device__ int   g_tok[MAX_ROWS];       // compact row -> token
__device__ int   g_cnt[N_EXP];
__device__ int   g_off[N_EXP];
__device__ int   g_pos[N_EXP];

__device__ __half g_x16[(size_t)MAX_T * D_MODEL];
__device__ __half g_w1[(size_t)N_EXP * D_MODEL * D_FF];
__device__ __half g_w2[(size_t)N_EXP * D_FF * D_MODEL];
__device__ __half g_h16[(size_t)MAX_ROWS * D_FF];

// ---------------- PTX helpers ----------------
__device__ __forceinline__ uint32_t smem_u32(const void* p) {
    uint32_t a;
    asm("{ .reg .u64 t; cvta.to.shared.u64 t, %1; cvt.u32.u64 %0, t; }" : "=r"(a) : "l"(p));
    return a;
}
#define CP_ASYNC16(dst, src) \
    asm volatile("cp.async.cg.shared.global [%0], [%1], 16;" :: "r"(dst), "l"(src))
#define CP_COMMIT() asm volatile("cp.async.commit_group;" ::: "memory")
#define CP_WAIT1()  asm volatile("cp.async.wait_group 1;" ::: "memory")
#define CP_WAIT0()  asm volatile("cp.async.wait_group 0;" ::: "memory")

__device__ __forceinline__ void ldsm_x4(uint32_t a, uint32_t& r0, uint32_t& r1, uint32_t& r2, uint32_t& r3) {
    asm volatile("ldmatrix.sync.aligned.m8n8.x4.shared.b16 {%0,%1,%2,%3}, [%4];"
                 : "=r"(r0), "=r"(r1), "=r"(r2), "=r"(r3) : "r"(a));
}
__device__ __forceinline__ void ldsm_x4_t(uint32_t a, uint32_t& r0, uint32_t& r1, uint32_t& r2, uint32_t& r3) {
    asm volatile("ldmatrix.sync.aligned.m8n8.x4.trans.shared.b16 {%0,%1,%2,%3}, [%4];"
                 : "=r"(r0), "=r"(r1), "=r"(r2), "=r"(r3) : "r"(a));
}
__device__ __forceinline__ void mma_fp16(float& d0, float& d1, float& d2, float& d3,
                                         uint32_t a0, uint32_t a1, uint32_t a2, uint32_t a3,
                                         uint32_t b0, uint32_t b1) {
    asm volatile("mma.sync.aligned.m16n8k16.row.col.f32.f16.f16.f32 "
                 "{%0,%1,%2,%3},{%4,%5,%6,%7},{%8,%9},{%0,%1,%2,%3};"
                 : "+f"(d0), "+f"(d1), "+f"(d2), "+f"(d3)
                 : "r"(a0), "r"(a1), "r"(a2), "r"(a3), "r"(b0), "r"(b1));
}

__device__ __forceinline__ void conv8(const float* __restrict__ src,
                                      __half* __restrict__ dst, size_t i) {
    float4 v0 = *reinterpret_cast<const float4*>(src + i);
    float4 v1 = *reinterpret_cast<const float4*>(src + i + 4);
    __half2 p[4];
    p[0] = __floats2half2_rn(v0.x, v0.y);
    p[1] = __floats2half2_rn(v0.z, v0.w);
    p[2] = __floats2half2_rn(v1.x, v1.y);
    p[3] = __floats2half2_rn(v1.z, v1.w);
    *reinterpret_cast<uint4*>(dst + i) = *reinterpret_cast<uint4*>(p);
}

// ---------------- small kernels ----------------
__global__ void zero_kernel() {
    int i = threadIdx.x;
    if (i < N_EXP) { g_cnt[i] = 0; g_pos[i] = 0; }
}

// Fused front end: gate | zero-out | conv x | conv W1 — role by blockIdx.x
#define GATE_CTAS  512
#define ZERO_CTAS  512
#define CONVX_CTAS 512
#define FRONT_CTAS 4096
__global__ void front_kernel(const float* __restrict__ x,
                             const float* __restrict__ Wg,
                             float* __restrict__ out, int T,
                             const float* __restrict__ W1src,
                             __half* __restrict__ w1dst, size_t nw,
                             __half* __restrict__ x16) {
    const int b = blockIdx.x;
    if (b < GATE_CTAS) {
        int gwarp = (b * 256 + threadIdx.x) >> 5;
        int lane  = threadIdx.x & 31;
        if (gwarp >= T) return;
        const float* xr = x + (size_t)gwarp * D_MODEL;
        float acc[N_EXP];
#pragma unroll
        for (int e = 0; e < N_EXP; e++) acc[e] = 0.f;
        for (int d = lane; d < D_MODEL; d += 32) {
            float xv = xr[d];
            const float* wr = Wg + d * N_EXP;
#pragma unroll
            for (int e = 0; e < N_EXP; e++) acc[e] += xv * wr[e];
        }
#pragma unroll
        for (int e = 0; e < N_EXP; e++)
#pragma unroll
            for (int o = 16; o > 0; o >>= 1)
                acc[e] += __shfl_xor_sync(0xFFFFFFFFu, acc[e], o);
        if (lane == 0) {
            int e0 = 0;
#pragma unroll
            for (int e = 1; e < N_EXP; e++) if (acc[e] > acc[e0]) e0 = e;
            int e1 = -1;
#pragma unroll
            for (int e = 0; e < N_EXP; e++) {
                if (e == e0) continue;
                if (e1 < 0 || acc[e] > acc[e1]) e1 = e;
            }
            float l0 = acc[e0], l1 = acc[e1];
            float z1 = __expf(l1 - l0);
            float s  = 1.f + z1;
            g_gw[2 * gwarp]     = 1.f / s;
            g_gw[2 * gwarp + 1] = z1  / s;
            g_geid[2 * gwarp]     = e0;
            g_geid[2 * gwarp + 1] = e1;
            atomicAdd(&g_cnt[e0], 1);
            atomicAdd(&g_cnt[e1], 1);
        }
    } else if (b < GATE_CTAS + ZERO_CTAS) {
        const int bb = b - GATE_CTAS;
        const size_t n = (size_t)T * D_MODEL;
        const size_t stride = (size_t)ZERO_CTAS * 256 * 4;
        for (size_t i = ((size_t)bb * 256 + threadIdx.x) * 4; i < n; i += stride) {
            float4 z = {0.f, 0.f, 0.f, 0.f};
            *reinterpret_cast<float4*>(out + i) = z;
        }
    } else if (b < GATE_CTAS + ZERO_CTAS + CONVX_CTAS) {
        const int bb = b - GATE_CTAS - ZERO_CTAS;
        const size_t n = (size_t)T * D_MODEL;
        const size_t stride = (size_t)CONVX_CTAS * 256 * 8;
        for (size_t i = ((size_t)bb * 256 + threadIdx.x) * 8; i < n; i += stride)
            conv8(x, x16, i);
    } else {
        const int bb = b - GATE_CTAS - ZERO_CTAS - CONVX_CTAS;
        const int nc = FRONT_CTAS - GATE_CTAS - ZERO_CTAS - CONVX_CTAS;   // 2560
        const size_t stride = (size_t)nc * 256 * 8;
        for (size_t i = ((size_t)bb * 256 + threadIdx.x) * 8; i < nw; i += stride)
            conv8(W1src, w1dst, i);
    }
}

__global__ void route_kernel(int T) {
    if (threadIdx.x == 0) {
        int s = 0;
#pragma unroll
        for (int e = 0; e < N_EXP; e++) { g_off[e] = s; s += g_cnt[e]; }
    }
    __syncthreads();
    int A = T * TOPK;
    for (int a = threadIdx.x; a < A; a += blockDim.x) {
        int e = g_geid[a];
        int p = atomicAdd(&g_pos[e], 1);
        int r = g_off[e] + p;
        g_tok[r] = a >> 1;
        g_rw[r]  = g_gw[a];
    }
}

// ---------------- HMMA grouped GEMM (3-stage, single barrier, templated BM) -------
// BM=128: 8 warps 2Mx4N, warp tile 64x32 (MF=4).  BM=64: warp tile 32x32 (MF=2).
// BN=128, BK=32, NSTAGE=3 for both.
#define A_PITCH   80
#define B_PITCH   272
#define B_BYTES   (32 * B_PITCH)           // 8704
#define NSTAGE    3

template <int BM, bool GATHER, bool RELU, bool ATOMIC_OUT, bool FUSECONV>
__global__ void __launch_bounds__(256, 2)
mma_gemm(const __half* __restrict__ A_g,
         const __half* __restrict__ B_g,
         const float* __restrict__ bias,
         float* __restrict__ Cf,
         __half* __restrict__ Ch,
         int K, int N,
         const float* __restrict__ cvt_src,
         __half* __restrict__ cvt_dst,
         size_t cvt_n) {
    constexpr int A_BYTES = BM * A_PITCH;
    constexpr int OFF_B   = A_BYTES;
    constexpr int STAGEB  = A_BYTES + B_BYTES;
    constexpr int MF      = BM / 32;        // m16 frags per warp
    constexpr int ARPT    = BM / 64;        // A rows loaded per thread

    if (FUSECONV && blockIdx.x == gridDim.x - 1) {
        const int cid = blockIdx.z * gridDim.y + blockIdx.y;
        const int nc  = gridDim.z * gridDim.y;
        const size_t stride = (size_t)nc * 256 * 8;
        for (size_t i = ((size_t)cid * 256 + threadIdx.x) * 8; i < cvt_n; i += stride)
            conv8(cvt_src, cvt_dst, i);
        return;
    }

    const int e   = blockIdx.z;
    const int cnt = g_cnt[e];
    const int m0  = blockIdx.y * BM;
    if (m0 >= cnt) return;
    const int off  = g_off[e];
    const int n0   = blockIdx.x * 128;
    const int rows = min(BM, cnt - m0);

    extern __shared__ uint8_t smem[];
    const uint32_t sm = smem_u32(smem);

    const int tid  = threadIdx.x;
    const int wid  = tid >> 5;
    const int lane = tid & 31;
    const int wm   = (wid >> 2) * (BM / 2);
    const int wn   = (wid & 3) * 32;

    // A source: ARPT rows/thread, 16B chunk acv
    const int ar   = tid >> 2;
    const int acv  = tid & 3;
    const char *pA[ARPT];
#pragma unroll
    for (int i = 0; i < ARPT; i++) {
        int r  = ar + 64 * i;
        int mr = min(r, rows - 1);
        int gr = off + m0 + mr;
        size_t srow = GATHER ? (size_t)g_tok[gr] : (size_t)gr;
        pA[i] = (const char*)(A_g + srow * K) + acv * 16;
    }
    // B source: 2 chunks/thread over 32 rows x 16 chunks
    const size_t ebase = (size_t)e * K * N;
    const char* pB_base = (const char*)(B_g + ebase + n0);
    const size_t bstride = (size_t)N * 2;
    int brow[2], bcol[2];
#pragma unroll
    for (int t = 0; t < 2; t++) {
        int idx = tid + 256 * t;
        brow[t] = idx >> 4;
        bcol[t] = idx & 15;
    }

    const int nch = K >> 5;

    auto issue = [&](int c, int s) {
        const uint32_t st = sm + s * STAGEB;
        const size_t ka = (size_t)c * 64;
#pragma unroll
        for (int i = 0; i < ARPT; i++) {
            uint32_t d = st + (ar + 64 * i) * A_PITCH + acv * 16;
            CP_ASYNC16(d, pA[i] + ka);
        }
#pragma unroll
        for (int t = 0; t < 2; t++) {
            uint32_t d = st + OFF_B + brow[t] * B_PITCH + bcol[t] * 16;
            size_t so = (size_t)(c * 32 + brow[t]) * bstride + bcol[t] * 16;
            CP_ASYNC16(d, pB_base + so);
        }
        CP_COMMIT();
    };

    float acc[MF][4][4];
#pragma unroll
    for (int a = 0; a < MF; a++)
#pragma unroll
        for (int b = 0; b < 4; b++)
#pragma unroll
            for (int r = 0; r < 4; r++) acc[a][b][r] = 0.f;

    issue(0, 0);
    issue(1, 1);
    int s_cur = 0;
    int s_nxt = 2;
    for (int c = 0; c < nch; c++) {
        if (c + 1 < nch) CP_WAIT1(); else CP_WAIT0();
        __syncthreads();
        if (c + 2 < nch) issue(c + 2, s_nxt);

        const uint32_t st = sm + s_cur * STAGEB;
#pragma unroll
        for (int ks = 0; ks < 2; ks++) {
            uint32_t bb[4][2];
            const uint32_t brw = ks * 16 + (lane & 15);
            const uint32_t bco = (wn + ((lane >> 4) * 8)) * 2;
#pragma unroll
            for (int p = 0; p < 2; p++) {
                uint32_t addr = st + OFF_B + brw * B_PITCH + bco + p * 32;
                ldsm_x4_t(addr, bb[2 * p][0], bb[2 * p][1], bb[2 * p + 1][0], bb[2 * p + 1][1]);
            }
            const uint32_t arow = wm + (lane & 15);
            const uint32_t acol = ((lane >> 4) * 8 + ks * 16) * 2;
#pragma unroll
            for (int mf = 0; mf < MF; mf++) {
                uint32_t aa[4];
                uint32_t addr = st + (arow + mf * 16) * A_PITCH + acol;
                ldsm_x4(addr, aa[0], aa[1], aa[2], aa[3]);
#pragma unroll
                for (int nb = 0; nb < 4; nb++) {
                    float* d = acc[mf][nb];
                    mma_fp16(d[0], d[1], d[2], d[3],
                             aa[0], aa[1], aa[2], aa[3], bb[nb][0], bb[nb][1]);
                }
            }
        }
        s_cur = (s_cur == 2) ? 0 : s_cur + 1;
        s_nxt = (s_nxt == 2) ? 0 : s_nxt + 1;
    }

    // ---- epilogue ----
    const float* bp = bias + (size_t)e * N + n0;
#pragma unroll
    for (int mf = 0; mf < MF; mf++)
#pragma unroll
        for (int nb = 0; nb < 4; nb++) {
            const int c  = wn + nb * 8 + (lane & 3) * 2;
            const float b0 = bp[c], b1 = bp[c + 1];
#pragma unroll
            for (int half = 0; half < 2; half++) {
                const int r = wm + mf * 16 + (lane >> 2) + half * 8;
                if (r < rows) {
                    float f0 = acc[mf][nb][half * 2]     + b0;
                    float f1 = acc[mf][nb][half * 2 + 1] + b1;
                    if (RELU) { f0 = fmaxf(f0, 0.f); f1 = fmaxf(f1, 0.f); }
                    const size_t grow = (size_t)(off + m0 + r);
                    if (ATOMIC_OUT) {
                        const int   t = g_tok[grow];
                        const float w = g_rw[grow];
                        float* op = Cf + (size_t)t * N + n0 + c;
                        atomicAdd(op,     w * f0);
                        atomicAdd(op + 1, w * f1);
                    } else {
                        const size_t o = grow * N + n0 + c;
                        __half2 hp = {__float2half_rn(f0), __float2half_rn(f1)};
                        *reinterpret_cast<__half2*>(Ch + o) = hp;
                    }
                }
            }
        }
}

// ---------------- launch ----------------
extern "C" void kernel_launch(void* const* d_in, const int* in_sizes, int n_in,
                              void* d_out, int out_size) {
    const float* x  = (const float*)d_in[0];
    const float* Wg = (const float*)d_in[1];
    const float* W1 = (const float*)d_in[2];
    const float* b1 = (const float*)d_in[3];
    const float* W2 = (const float*)d_in[4];
    const float* b2 = (const float*)d_in[5];
    float* out = (float*)d_out;

    const int T = in_sizes[0] / D_MODEL;   // 4096

    __half *x16, *w1, *w2, *h16;
    cudaGetSymbolAddress((void**)&x16, g_x16);
    cudaGetSymbolAddress((void**)&w1,  g_w1);
    cudaGetSymbolAddress((void**)&w2,  g_w2);
    cudaGetSymbolAddress((void**)&h16, g_h16);

    constexpr int SMEM1 = NSTAGE * (128 * A_PITCH + B_BYTES);   // 56832
    constexpr int SMEM2 = NSTAGE * (64 * A_PITCH + B_BYTES);    // 41472

    cudaFuncSetAttribute(mma_gemm<128, true, true, false, true>,
                         cudaFuncAttributeMaxDynamicSharedMemorySize, SMEM1);
    cudaFuncSetAttribute(mma_gemm<64, false, false, true, false>,
                         cudaFuncAttributeMaxDynamicSharedMemorySize, SMEM2);

    size_t nw = (size_t)N_EXP * D_MODEL * D_FF;

    zero_kernel<<<1, 32>>>();
    front_kernel<<<FRONT_CTAS, 256>>>(x, Wg, out, T, W1, w1, nw, x16);
    route_kernel<<<1, 256>>>(T);

    // GEMM1: h = relu(x @ W1 + b1), fp16 out. x==last CTAs convert W2 (interleaved).
    mma_gemm<128, true, true, false, true>
        <<<dim3(D_FF / 128 + 1, MAX_T / 128, N_EXP), 256, SMEM1>>>(
        x16, w1, b1, nullptr, h16, D_MODEL, D_FF, W2, w2, nw);
    // GEMM2: BM=64 for better wave packing; weighted-scatter into out via atomics
    mma_gemm<64, false, false, true, false>
        <<<dim3(D_MODEL / 128, MAX_T / 64, N_EXP), 256, SMEM2>>>(
        h16, w2, b2, out, nullptr, D_FF, D_MODEL, nullptr, nullptr, 0);
}

// round 15
// speedup vs baseline: 1.0218x; 1.0218x over previous
#include <cuda_runtime.h>
#include <cuda_fp16.h>
#include <cstdint>

#define D_MODEL 1024
#define D_FF    4096
#define N_EXP   8
#define TOPK    2
#define MAX_T   4096
#define MAX_ROWS (MAX_T * TOPK)

// ---------------- scratch (device globals; no allocation allowed) ----------------
__device__ float g_gw[MAX_T * TOPK];
__device__ int   g_geid[MAX_T * TOPK];
__device__ float g_rw[MAX_ROWS];        // compact row -> gate weight
__device__ int   g_tok[MAX_ROWS];       // compact row -> token
__device__ int   g_cnt[N_EXP];
__device__ int   g_off[N_EXP];
__device__ int   g_pos[N_EXP];

__device__ __half g_x16[(size_t)MAX_T * D_MODEL];
__device__ __half g_w1[(size_t)N_EXP * D_MODEL * D_FF];
__device__ __half g_w2[(size_t)N_EXP * D_FF * D_MODEL];
__device__ __half g_h16[(size_t)MAX_ROWS * D_FF];

// ---------------- PTX helpers ----------------
__device__ __forceinline__ uint32_t smem_u32(const void* p) {
    uint32_t a;
    asm("{ .reg .u64 t; cvta.to.shared.u64 t, %1; cvt.u32.u64 %0, t; }" : "=r"(a) : "l"(p));
    return a;
}
#define CP_ASYNC16(dst, src) \
    asm volatile("cp.async.cg.shared.global [%0], [%1], 16;" :: "r"(dst), "l"(src))
#define CP_COMMIT() asm volatile("cp.async.commit_group;" ::: "memory")
#define CP_WAIT1()  asm volatile("cp.async.wait_group 1;" ::: "memory")
#define CP_WAIT0()  asm volatile("cp.async.wait_group 0;" ::: "memory")

__device__ __forceinline__ void ldsm_x4(uint32_t a, uint32_t& r0, uint32_t& r1, uint32_t& r2, uint32_t& r3) {
    asm volatile("ldmatrix.sync.aligned.m8n8.x4.shared.b16 {%0,%1,%2,%3}, [%4];"
                 : "=r"(r0), "=r"(r1), "=r"(r2), "=r"(r3) : "r"(a));
}
__device__ __forceinline__ void ldsm_x4_t(uint32_t a, uint32_t& r0, uint32_t& r1, uint32_t& r2, uint32_t& r3) {
    asm volatile("ldmatrix.sync.aligned.m8n8.x4.trans.shared.b16 {%0,%1,%2,%3}, [%4];"
                 : "=r"(r0), "=r"(r1), "=r"(r2), "=r"(r3) : "r"(a));
}
__device__ __forceinline__ void mma_fp16(float& d0, float& d1, float& d2, float& d3,
                                         uint32_t a0, uint32_t a1, uint32_t a2, uint32_t a3,
                                         uint32_t b0, uint32_t b1) {
    asm volatile("mma.sync.aligned.m16n8k16.row.col.f32.f16.f16.f32 "
                 "{%0,%1,%2,%3},{%4,%5,%6,%7},{%8,%9},{%0,%1,%2,%3};"
                 : "+f"(d0), "+f"(d1), "+f"(d2), "+f"(d3)
                 : "r"(a0), "r"(a1), "r"(a2), "r"(a3), "r"(b0), "r"(b1));
}

__device__ __forceinline__ void conv8(const float* __restrict__ src,
                                      __half* __restrict__ dst, size_t i) {
    float4 v0 = *reinterpret_cast<const float4*>(src + i);
    float4 v1 = *reinterpret_cast<const float4*>(src + i + 4);
    __half2 p[4];
    p[0] = __floats2half2_rn(v0.x, v0.y);
    p[1] = __floats2half2_rn(v0.z, v0.w);
    p[2] = __floats2half2_rn(v1.x, v1.y);
    p[3] = __floats2half2_rn(v1.z, v1.w);
    *reinterpret_cast<uint4*>(dst + i) = *reinterpret_cast<uint4*>(p);
}

// ---------------- small kernels ----------------
__global__ void zero_kernel() {
    int i = threadIdx.x;
    if (i < N_EXP) { g_cnt[i] = 0; g_pos[i] = 0; }
}

// Fused front end: gate | zero-out | conv x | conv W1 — role by blockIdx.x
#define GATE_CTAS  512
#define ZERO_CTAS  512
#define CONVX_CTAS 512
#define FRONT_CTAS 4096
__global__ void front_kernel(const float* __restrict__ x,
                             const float* __restrict__ Wg,
                             float* __restrict__ out, int T,
                             const float* __restrict__ W1src,
                             __half* __restrict__ w1dst, size_t nw,
                             __half* __restrict__ x16) {
    const int b = blockIdx.x;
    if (b < GATE_CTAS) {
        int gwarp = (b * 256 + threadIdx.x) >> 5;
        int lane  = threadIdx.x & 31;
        if (gwarp >= T) return;
        const float* xr = x + (size_t)gwarp * D_MODEL;
        float acc[N_EXP];
#pragma unroll
        for (int e = 0; e < N_EXP; e++) acc[e] = 0.f;
        for (int d = lane; d < D_MODEL; d += 32) {
            float xv = xr[d];
            const float* wr = Wg + d * N_EXP;
#pragma unroll
            for (int e = 0; e < N_EXP; e++) acc[e] += xv * wr[e];
        }
#pragma unroll
        for (int e = 0; e < N_EXP; e++)
#pragma unroll
            for (int o = 16; o > 0; o >>= 1)
                acc[e] += __shfl_xor_sync(0xFFFFFFFFu, acc[e], o);
        if (lane == 0) {
            int e0 = 0;
#pragma unroll
            for (int e = 1; e < N_EXP; e++) if (acc[e] > acc[e0]) e0 = e;
            int e1 = -1;
#pragma unroll
            for (int e = 0; e < N_EXP; e++) {
                if (e == e0) continue;
                if (e1 < 0 || acc[e] > acc[e1]) e1 = e;
            }
            float l0 = acc[e0], l1 = acc[e1];
            float z1 = __expf(l1 - l0);
            float s  = 1.f + z1;
            g_gw[2 * gwarp]     = 1.f / s;
            g_gw[2 * gwarp + 1] = z1  / s;
            g_geid[2 * gwarp]     = e0;
            g_geid[2 * gwarp + 1] = e1;
            atomicAdd(&g_cnt[e0], 1);
            atomicAdd(&g_cnt[e1], 1);
        }
    } else if (b < GATE_CTAS + ZERO_CTAS) {
        const int bb = b - GATE_CTAS;
        const size_t n = (size_t)T * D_MODEL;
        const size_t stride = (size_t)ZERO_CTAS * 256 * 4;
        for (size_t i = ((size_t)bb * 256 + threadIdx.x) * 4; i < n; i += stride) {
            float4 z = {0.f, 0.f, 0.f, 0.f};
            *reinterpret_cast<float4*>(out + i) = z;
        }
    } else if (b < GATE_CTAS + ZERO_CTAS + CONVX_CTAS) {
        const int bb = b - GATE_CTAS - ZERO_CTAS;
        const size_t n = (size_t)T * D_MODEL;
        const size_t stride = (size_t)CONVX_CTAS * 256 * 8;
        for (size_t i = ((size_t)bb * 256 + threadIdx.x) * 8; i < n; i += stride)
            conv8(x, x16, i);
    } else {
        const int bb = b - GATE_CTAS - ZERO_CTAS - CONVX_CTAS;
        const int nc = FRONT_CTAS - GATE_CTAS - ZERO_CTAS - CONVX_CTAS;   // 2560
        const size_t stride = (size_t)nc * 256 * 8;
        for (size_t i = ((size_t)bb * 256 + threadIdx.x) * 8; i < nw; i += stride)
            conv8(W1src, w1dst, i);
    }
}

__global__ void route_kernel(int T) {
    if (threadIdx.x == 0) {
        int s = 0;
#pragma unroll
        for (int e = 0; e < N_EXP; e++) { g_off[e] = s; s += g_cnt[e]; }
    }
    __syncthreads();
    int A = T * TOPK;
    for (int a = threadIdx.x; a < A; a += blockDim.x) {
        int e = g_geid[a];
        int p = atomicAdd(&g_pos[e], 1);
        int r = g_off[e] + p;
        g_tok[r] = a >> 1;
        g_rw[r]  = g_gw[a];
    }
}

// ---------------- HMMA grouped GEMM (3-stage, single barrier, optional split-K) ----
// BM=128, BN=128, BK=32, NSTAGE=3, 8 warps (2Mx4N), warp tile 64x32.
// SPLITK>1: blockIdx.y = m_tile*SPLITK + kidx; each split covers K/SPLITK and
// atomicAdds its partial into out (requires ATOMIC_OUT). Bias added by kidx==0.
#define A_PITCH   80
#define B_PITCH   272
#define A_BYTES   (128 * A_PITCH)          // 10240
#define B_BYTES   (32 * B_PITCH)           // 8704
#define OFF_B     A_BYTES
#define STAGEB    (A_BYTES + B_BYTES)      // 18944
#define NSTAGE    3
#define SMEM_SZ   (NSTAGE * STAGEB)        // 56832 (2 CTAs/SM)

template <int SPLITK, bool GATHER, bool RELU, bool ATOMIC_OUT, bool FUSECONV>
__global__ void __launch_bounds__(256, 2)
mma_gemm(const __half* __restrict__ A_g,
         const __half* __restrict__ B_g,
         const float* __restrict__ bias,
         float* __restrict__ Cf,
         __half* __restrict__ Ch,
         int K, int N,
         const float* __restrict__ cvt_src,
         __half* __restrict__ cvt_dst,
         size_t cvt_n) {
    if (FUSECONV && blockIdx.x == gridDim.x - 1) {
        const int cid = blockIdx.z * gridDim.y + blockIdx.y;
        const int nc  = gridDim.z * gridDim.y;
        const size_t stride = (size_t)nc * 256 * 8;
        for (size_t i = ((size_t)cid * 256 + threadIdx.x) * 8; i < cvt_n; i += stride)
            conv8(cvt_src, cvt_dst, i);
        return;
    }

    const int e    = blockIdx.z;
    const int cnt  = g_cnt[e];
    const int kidx = (SPLITK > 1) ? (blockIdx.y % SPLITK) : 0;
    const int m0   = ((SPLITK > 1) ? (blockIdx.y / SPLITK) : blockIdx.y) * 128;
    if (m0 >= cnt) return;
    const int off  = g_off[e];
    const int n0   = blockIdx.x * 128;
    const int rows = min(128, cnt - m0);
    const int KS   = K / SPLITK;            // K range per split
    const int kbase = kidx * KS;

    extern __shared__ uint8_t smem[];
    const uint32_t sm = smem_u32(smem);

    const int tid  = threadIdx.x;
    const int wid  = tid >> 5;
    const int lane = tid & 31;
    const int wm   = (wid >> 2) * 64;
    const int wn   = (wid & 3) * 32;

    // A source: 2 rows/thread, 16B chunk acv
    const int ar   = tid >> 2;
    const int acv  = tid & 3;
    const char *pA[2];
#pragma unroll
    for (int i = 0; i < 2; i++) {
        int r  = ar + 64 * i;
        int mr = min(r, rows - 1);
        int gr = off + m0 + mr;
        size_t srow = GATHER ? (size_t)g_tok[gr] : (size_t)gr;
        pA[i] = (const char*)(A_g + srow * K + kbase) + acv * 16;
    }
    // B source: 2 chunks/thread over 32 rows x 16 chunks
    const size_t ebase = (size_t)e * K * N;
    const char* pB_base = (const char*)(B_g + ebase + (size_t)kbase * N + n0);
    const size_t bstride = (size_t)N * 2;
    int brow[2], bcol[2];
#pragma unroll
    for (int t = 0; t < 2; t++) {
        int idx = tid + 256 * t;
        brow[t] = idx >> 4;
        bcol[t] = idx & 15;
    }

    const int nch = KS >> 5;

    auto issue = [&](int c, int s) {
        const uint32_t st = sm + s * STAGEB;
        const size_t ka = (size_t)c * 64;
#pragma unroll
        for (int i = 0; i < 2; i++) {
            uint32_t d = st + (ar + 64 * i) * A_PITCH + acv * 16;
            CP_ASYNC16(d, pA[i] + ka);
        }
#pragma unroll
        for (int t = 0; t < 2; t++) {
            uint32_t d = st + OFF_B + brow[t] * B_PITCH + bcol[t] * 16;
            size_t so = (size_t)(c * 32 + brow[t]) * bstride + bcol[t] * 16;
            CP_ASYNC16(d, pB_base + so);
        }
        CP_COMMIT();
    };

    float acc[4][4][4];
#pragma unroll
    for (int a = 0; a < 4; a++)
#pragma unroll
        for (int b = 0; b < 4; b++)
#pragma unroll
            for (int r = 0; r < 4; r++) acc[a][b][r] = 0.f;

    issue(0, 0);
    issue(1, 1);
    int s_cur = 0;
    int s_nxt = 2;
    for (int c = 0; c < nch; c++) {
        if (c + 1 < nch) CP_WAIT1(); else CP_WAIT0();
        __syncthreads();
        if (c + 2 < nch) issue(c + 2, s_nxt);

        const uint32_t st = sm + s_cur * STAGEB;
#pragma unroll
        for (int ks = 0; ks < 2; ks++) {
            uint32_t bb[4][2];
            const uint32_t brw = ks * 16 + (lane & 15);
            const uint32_t bco = (wn + ((lane >> 4) * 8)) * 2;
#pragma unroll
            for (int p = 0; p < 2; p++) {
                uint32_t addr = st + OFF_B + brw * B_PITCH + bco + p * 32;
                ldsm_x4_t(addr, bb[2 * p][0], bb[2 * p][1], bb[2 * p + 1][0], bb[2 * p + 1][1]);
            }
            const uint32_t arow = wm + (lane & 15);
            const uint32_t acol = ((lane >> 4) * 8 + ks * 16) * 2;
#pragma unroll
            for (int mf = 0; mf < 4; mf++) {
                uint32_t aa[4];
                uint32_t addr = st + (arow + mf * 16) * A_PITCH + acol;
                ldsm_x4(addr, aa[0], aa[1], aa[2], aa[3]);
#pragma unroll
                for (int nb = 0; nb < 4; nb++) {
                    float* d = acc[mf][nb];
                    mma_fp16(d[0], d[1], d[2], d[3],
                             aa[0], aa[1], aa[2], aa[3], bb[nb][0], bb[nb][1]);
                }
            }
        }
        s_cur = (s_cur == 2) ? 0 : s_cur + 1;
        s_nxt = (s_nxt == 2) ? 0 : s_nxt + 1;
    }

    // ---- epilogue ----
    const float* bp = bias + (size_t)e * N + n0;
    const bool addb = (kidx == 0);
#pragma unroll
    for (int mf = 0; mf < 4; mf++)
#pragma unroll
        for (int nb = 0; nb < 4; nb++) {
            const int c  = wn + nb * 8 + (lane & 3) * 2;
            const float b0 = addb ? bp[c]     : 0.f;
            const float b1 = addb ? bp[c + 1] : 0.f;
#pragma unroll
            for (int half = 0; half < 2; half++) {
                const int r = wm + mf * 16 + (lane >> 2) + half * 8;
                if (r < rows) {
                    float f0 = acc[mf][nb][half * 2]     + b0;
                    float f1 = acc[mf][nb][half * 2 + 1] + b1;
                    if (RELU) { f0 = fmaxf(f0, 0.f); f1 = fmaxf(f1, 0.f); }
                    const size_t grow = (size_t)(off + m0 + r);
                    if (ATOMIC_OUT) {
                        const int   t = g_tok[grow];
                        const float w = g_rw[grow];
                        float* op = Cf + (size_t)t * N + n0 + c;
                        atomicAdd(op,     w * f0);
                        atomicAdd(op + 1, w * f1);
                    } else {
                        const size_t o = grow * N + n0 + c;
                        __half2 hp = {__float2half_rn(f0), __float2half_rn(f1)};
                        *reinterpret_cast<__half2*>(Ch + o) = hp;
                    }
                }
            }
        }
}

// ---------------- launch ----------------
extern "C" void kernel_launch(void* const* d_in, const int* in_sizes, int n_in,
                              void* d_out, int out_size) {
    const float* x  = (const float*)d_in[0];
    const float* Wg = (const float*)d_in[1];
    const float* W1 = (const float*)d_in[2];
    const float* b1 = (const float*)d_in[3];
    const float* W2 = (const float*)d_in[4];
    const float* b2 = (const float*)d_in[5];
    float* out = (float*)d_out;

    const int T = in_sizes[0] / D_MODEL;   // 4096

    __half *x16, *w1, *w2, *h16;
    cudaGetSymbolAddress((void**)&x16, g_x16);
    cudaGetSymbolAddress((void**)&w1,  g_w1);
    cudaGetSymbolAddress((void**)&w2,  g_w2);
    cudaGetSymbolAddress((void**)&h16, g_h16);

    cudaFuncSetAttribute(mma_gemm<1, true, true, false, true>,
                         cudaFuncAttributeMaxDynamicSharedMemorySize, SMEM_SZ);
    cudaFuncSetAttribute(mma_gemm<2, false, false, true, false>,
                         cudaFuncAttributeMaxDynamicSharedMemorySize, SMEM_SZ);

    size_t nw = (size_t)N_EXP * D_MODEL * D_FF;

    zero_kernel<<<1, 32>>>();
    front_kernel<<<FRONT_CTAS, 256>>>(x, Wg, out, T, W1, w1, nw, x16);
    route_kernel<<<1, 256>>>(T);

    // GEMM1: h = relu(x @ W1 + b1), fp16 out. x==last CTAs convert W2 (interleaved).
    mma_gemm<1, true, true, false, true>
        <<<dim3(D_FF / 128 + 1, MAX_T / 128, N_EXP), 256, SMEM_SZ>>>(
        x16, w1, b1, nullptr, h16, D_MODEL, D_FF, W2, w2, nw);
    // GEMM2: split-K=2 (y = m_tile*2 + kidx), atomic weighted-scatter into out
    mma_gemm<2, false, false, true, false>
        <<<dim3(D_MODEL / 128, (MAX_T / 128) * 2, N_EXP), 256, SMEM_SZ>>>(
        h16, w2, b2, out, nullptr, D_FF, D_MODEL, nullptr, nullptr, 0);
}

// round 16
// speedup vs baseline: 1.0637x; 1.0410x over previous
#include <cuda_runtime.h>
#include <cuda_fp16.h>
#include <cstdint>

#define D_MODEL 1024
#define D_FF    4096
#define N_EXP   8
#define TOPK    2
#define MAX_T   4096
#define MAX_ROWS (MAX_T * TOPK)

// ---------------- scratch (device globals; no allocation allowed) ----------------
__device__ float g_gw[MAX_T * TOPK];
__device__ int   g_geid[MAX_T * TOPK];
__device__ float g_rw[MAX_ROWS];        // compact row -> gate weight
__device__ int   g_tok[MAX_ROWS];       // compact row -> token
__device__ int   g_cnt[N_EXP];          // written ONLY by route_kernel (no reset needed)
__device__ int   g_off[N_EXP];

__device__ __half g_x16[(size_t)MAX_T * D_MODEL];
__device__ __half g_w1[(size_t)N_EXP * D_MODEL * D_FF];
__device__ __half g_w2[(size_t)N_EXP * D_FF * D_MODEL];
__device__ __half g_h16[(size_t)MAX_ROWS * D_FF];

// ---------------- PTX helpers ----------------
__device__ __forceinline__ uint32_t smem_u32(const void* p) {
    uint32_t a;
    asm("{ .reg .u64 t; cvta.to.shared.u64 t, %1; cvt.u32.u64 %0, t; }" : "=r"(a) : "l"(p));
    return a;
}
#define CP_ASYNC16(dst, src) \
    asm volatile("cp.async.cg.shared.global [%0], [%1], 16;" :: "r"(dst), "l"(src))
#define CP_COMMIT() asm volatile("cp.async.commit_group;" ::: "memory")
#define CP_WAIT1()  asm volatile("cp.async.wait_group 1;" ::: "memory")
#define CP_WAIT0()  asm volatile("cp.async.wait_group 0;" ::: "memory")

__device__ __forceinline__ void ldsm_x4(uint32_t a, uint32_t& r0, uint32_t& r1, uint32_t& r2, uint32_t& r3) {
    asm volatile("ldmatrix.sync.aligned.m8n8.x4.shared.b16 {%0,%1,%2,%3}, [%4];"
                 : "=r"(r0), "=r"(r1), "=r"(r2), "=r"(r3) : "r"(a));
}
__device__ __forceinline__ void ldsm_x4_t(uint32_t a, uint32_t& r0, uint32_t& r1, uint32_t& r2, uint32_t& r3) {
    asm volatile("ldmatrix.sync.aligned.m8n8.x4.trans.shared.b16 {%0,%1,%2,%3}, [%4];"
                 : "=r"(r0), "=r"(r1), "=r"(r2), "=r"(r3) : "r"(a));
}
__device__ __forceinline__ void mma_fp16(float& d0, float& d1, float& d2, float& d3,
                                         uint32_t a0, uint32_t a1, uint32_t a2, uint32_t a3,
                                         uint32_t b0, uint32_t b1) {
    asm volatile("mma.sync.aligned.m16n8k16.row.col.f32.f16.f16.f32 "
                 "{%0,%1,%2,%3},{%4,%5,%6,%7},{%8,%9},{%0,%1,%2,%3};"
                 : "+f"(d0), "+f"(d1), "+f"(d2), "+f"(d3)
                 : "r"(a0), "r"(a1), "r"(a2), "r"(a3), "r"(b0), "r"(b1));
}

__device__ __forceinline__ void conv8(const float* __restrict__ src,
                                      __half* __restrict__ dst, size_t i) {
    float4 v0 = *reinterpret_cast<const float4*>(src + i);
    float4 v1 = *reinterpret_cast<const float4*>(src + i + 4);
    __half2 p[4];
    p[0] = __floats2half2_rn(v0.x, v0.y);
    p[1] = __floats2half2_rn(v0.z, v0.w);
    p[2] = __floats2half2_rn(v1.x, v1.y);
    p[3] = __floats2half2_rn(v1.z, v1.w);
    *reinterpret_cast<uint4*>(dst + i) = *reinterpret_cast<uint4*>(p);
}

// ---------------- front end: gate | zero-out | conv x | conv W1 -------------------
#define GATE_CTAS  512
#define ZERO_CTAS  512
#define CONVX_CTAS 512
#define FRONT_CTAS 4096
__global__ void front_kernel(const float* __restrict__ x,
                             const float* __restrict__ Wg,
                             float* __restrict__ out, int T,
                             const float* __restrict__ W1src,
                             __half* __restrict__ w1dst, size_t nw,
                             __half* __restrict__ x16) {
    const int b = blockIdx.x;
    if (b < GATE_CTAS) {
        int gwarp = (b * 256 + threadIdx.x) >> 5;
        int lane  = threadIdx.x & 31;
        if (gwarp >= T) return;
        const float* xr = x + (size_t)gwarp * D_MODEL;
        float acc[N_EXP];
#pragma unroll
        for (int e = 0; e < N_EXP; e++) acc[e] = 0.f;
        for (int d = lane; d < D_MODEL; d += 32) {
            float xv = xr[d];
            const float* wr = Wg + d * N_EXP;
#pragma unroll
            for (int e = 0; e < N_EXP; e++) acc[e] += xv * wr[e];
        }
#pragma unroll
        for (int e = 0; e < N_EXP; e++)
#pragma unroll
            for (int o = 16; o > 0; o >>= 1)
                acc[e] += __shfl_xor_sync(0xFFFFFFFFu, acc[e], o);
        if (lane == 0) {
            int e0 = 0;
#pragma unroll
            for (int e = 1; e < N_EXP; e++) if (acc[e] > acc[e0]) e0 = e;
            int e1 = -1;
#pragma unroll
            for (int e = 0; e < N_EXP; e++) {
                if (e == e0) continue;
                if (e1 < 0 || acc[e] > acc[e1]) e1 = e;
            }
            float l0 = acc[e0], l1 = acc[e1];
            float z1 = __expf(l1 - l0);
            float s  = 1.f + z1;
            g_gw[2 * gwarp]     = 1.f / s;
            g_gw[2 * gwarp + 1] = z1  / s;
            g_geid[2 * gwarp]     = e0;
            g_geid[2 * gwarp + 1] = e1;
        }
    } else if (b < GATE_CTAS + ZERO_CTAS) {
        const int bb = b - GATE_CTAS;
        const size_t n = (size_t)T * D_MODEL;
        const size_t stride = (size_t)ZERO_CTAS * 256 * 4;
        for (size_t i = ((size_t)bb * 256 + threadIdx.x) * 4; i < n; i += stride) {
            float4 z = {0.f, 0.f, 0.f, 0.f};
            *reinterpret_cast<float4*>(out + i) = z;
        }
    } else if (b < GATE_CTAS + ZERO_CTAS + CONVX_CTAS) {
        const int bb = b - GATE_CTAS - ZERO_CTAS;
        const size_t n = (size_t)T * D_MODEL;
        const size_t stride = (size_t)CONVX_CTAS * 256 * 8;
        for (size_t i = ((size_t)bb * 256 + threadIdx.x) * 8; i < n; i += stride)
            conv8(x, x16, i);
    } else {
        const int bb = b - GATE_CTAS - ZERO_CTAS - CONVX_CTAS;
        const int nc = FRONT_CTAS - GATE_CTAS - ZERO_CTAS - CONVX_CTAS;   // 2560
        const size_t stride = (size_t)nc * 256 * 8;
        for (size_t i = ((size_t)bb * 256 + threadIdx.x) * 8; i < nw; i += stride)
            conv8(W1src, w1dst, i);
    }
}

// route: single block counts assignments, scans, assigns compact rows.
// g_cnt/g_off are written fresh every call (no zero_kernel needed).
__global__ void route_kernel(int T) {
    __shared__ int scnt[N_EXP], soff[N_EXP], spos[N_EXP];
    const int tid = threadIdx.x;
    if (tid < N_EXP) scnt[tid] = 0;
    __syncthreads();
    const int A = T * TOPK;
    for (int a = tid; a < A; a += blockDim.x)
        atomicAdd(&scnt[g_geid[a]], 1);
    __syncthreads();
    if (tid == 0) {
        int s = 0;
#pragma unroll
        for (int e = 0; e < N_EXP; e++) {
            soff[e] = s;
            spos[e] = 0;
            g_cnt[e] = scnt[e];
            g_off[e] = s;
            s += scnt[e];
        }
    }
    __syncthreads();
    for (int a = tid; a < A; a += blockDim.x) {
        int e = g_geid[a];
        int p = atomicAdd(&spos[e], 1);
        int r = soff[e] + p;
        g_tok[r] = a >> 1;
        g_rw[r]  = g_gw[a];
    }
}

// ---------------- HMMA grouped GEMM (3-stage, single barrier, optional split-K) ----
// BM=128, BN=128, BK=32, NSTAGE=3, 8 warps (2Mx4N), warp tile 64x32.
#define A_PITCH   80
#define B_PITCH   272
#define A_BYTES   (128 * A_PITCH)          // 10240
#define B_BYTES   (32 * B_PITCH)           // 8704
#define OFF_B     A_BYTES
#define STAGEB    (A_BYTES + B_BYTES)      // 18944
#define NSTAGE    3
#define SMEM_SZ   (NSTAGE * STAGEB)        // 56832 (2 CTAs/SM)

template <int SPLITK, bool GATHER, bool RELU, bool ATOMIC_OUT, bool FUSECONV>
__global__ void __launch_bounds__(256, 2)
mma_gemm(const __half* __restrict__ A_g,
         const __half* __restrict__ B_g,
         const float* __restrict__ bias,
         float* __restrict__ Cf,
         __half* __restrict__ Ch,
         int K, int N,
         const float* __restrict__ cvt_src,
         __half* __restrict__ cvt_dst,
         size_t cvt_n) {
    if (FUSECONV && blockIdx.x == gridDim.x - 1) {
        const int cid = blockIdx.z * gridDim.y + blockIdx.y;
        const int nc  = gridDim.z * gridDim.y;
        const size_t stride = (size_t)nc * 256 * 8;
        for (size_t i = ((size_t)cid * 256 + threadIdx.x) * 8; i < cvt_n; i += stride)
            conv8(cvt_src, cvt_dst, i);
        return;
    }

    const int e    = blockIdx.z;
    const int cnt  = g_cnt[e];
    const int kidx = (SPLITK > 1) ? (blockIdx.y % SPLITK) : 0;
    const int m0   = ((SPLITK > 1) ? (blockIdx.y / SPLITK) : blockIdx.y) * 128;
    if (m0 >= cnt) return;
    const int off  = g_off[e];
    const int n0   = blockIdx.x * 128;
    const int rows = min(128, cnt - m0);
    const int KS   = K / SPLITK;
    const int kbase = kidx * KS;

    extern __shared__ uint8_t smem[];
    const uint32_t sm = smem_u32(smem);

    const int tid  = threadIdx.x;
    const int wid  = tid >> 5;
    const int lane = tid & 31;
    const int wm   = (wid >> 2) * 64;
    const int wn   = (wid & 3) * 32;

    // A source: 2 rows/thread, 16B chunk acv
    const int ar   = tid >> 2;
    const int acv  = tid & 3;
    const char *pA[2];
#pragma unroll
    for (int i = 0; i < 2; i++) {
        int r  = ar + 64 * i;
        int mr = min(r, rows - 1);
        int gr = off + m0 + mr;
        size_t srow = GATHER ? (size_t)g_tok[gr] : (size_t)gr;
        pA[i] = (const char*)(A_g + srow * K + kbase) + acv * 16;
    }
    // B source: 2 chunks/thread over 32 rows x 16 chunks
    const size_t ebase = (size_t)e * K * N;
    const char* pB_base = (const char*)(B_g + ebase + (size_t)kbase * N + n0);
    const size_t bstride = (size_t)N * 2;
    int brow[2], bcol[2];
#pragma unroll
    for (int t = 0; t < 2; t++) {
        int idx = tid + 256 * t;
        brow[t] = idx >> 4;
        bcol[t] = idx & 15;
    }

    const int nch = KS >> 5;

    auto issue = [&](int c, int s) {
        const uint32_t st = sm + s * STAGEB;
        const size_t ka = (size_t)c * 64;
#pragma unroll
        for (int i = 0; i < 2; i++) {
            uint32_t d = st + (ar + 64 * i) * A_PITCH + acv * 16;
            CP_ASYNC16(d, pA[i] + ka);
        }
#pragma unroll
        for (int t = 0; t < 2; t++) {
            uint32_t d = st + OFF_B + brow[t] * B_PITCH + bcol[t] * 16;
            size_t so = (size_t)(c * 32 + brow[t]) * bstride + bcol[t] * 16;
            CP_ASYNC16(d, pB_base + so);
        }
        CP_COMMIT();
    };

    float acc[4][4][4];
#pragma unroll
    for (int a = 0; a < 4; a++)
#pragma unroll
        for (int b = 0; b < 4; b++)
#pragma unroll
            for (int r = 0; r < 4; r++) acc[a][b][r] = 0.f;

    issue(0, 0);
    issue(1, 1);
    int s_cur = 0;
    int s_nxt = 2;
    for (int c = 0; c < nch; c++) {
        if (c + 1 < nch) CP_WAIT1(); else CP_WAIT0();
        __syncthreads();
        if (c + 2 < nch) issue(c + 2, s_nxt);

        const uint32_t st = sm + s_cur * STAGEB;
#pragma unroll
        for (int ks = 0; ks < 2; ks++) {
            uint32_t bb[4][2];
            const uint32_t brw = ks * 16 + (lane & 15);
            const uint32_t bco = (wn + ((lane >> 4) * 8)) * 2;
#pragma unroll
            for (int p = 0; p < 2; p++) {
                uint32_t addr = st + OFF_B + brw * B_PITCH + bco + p * 32;
                ldsm_x4_t(addr, bb[2 * p][0], bb[2 * p][1], bb[2 * p + 1][0], bb[2 * p + 1][1]);
            }
            const uint32_t arow = wm + (lane & 15);
            const uint32_t acol = ((lane >> 4) * 8 + ks * 16) * 2;
#pragma unroll
            for (int mf = 0; mf < 4; mf++) {
                uint32_t aa[4];
                uint32_t addr = st + (arow + mf * 16) * A_PITCH + acol;
                ldsm_x4(addr, aa[0], aa[1], aa[2], aa[3]);
#pragma unroll
                for (int nb = 0; nb < 4; nb++) {
                    float* d = acc[mf][nb];
                    mma_fp16(d[0], d[1], d[2], d[3],
                             aa[0], aa[1], aa[2], aa[3], bb[nb][0], bb[nb][1]);
                }
            }
        }
        s_cur = (s_cur == 2) ? 0 : s_cur + 1;
        s_nxt = (s_nxt == 2) ? 0 : s_nxt + 1;
    }

    // ---- epilogue ----
    const float* bp = bias + (size_t)e * N + n0;
    const bool addb = (kidx == 0);
#pragma unroll
    for (int mf = 0; mf < 4; mf++)
#pragma unroll
        for (int nb = 0; nb < 4; nb++) {
            const int c  = wn + nb * 8 + (lane & 3) * 2;
            const float b0 = addb ? bp[c]     : 0.f;
            const float b1 = addb ? bp[c + 1] : 0.f;
#pragma unroll
            for (int half = 0; half < 2; half++) {
                const int r = wm + mf * 16 + (lane >> 2) + half * 8;
                if (r < rows) {
                    float f0 = acc[mf][nb][half * 2]     + b0;
                    float f1 = acc[mf][nb][half * 2 + 1] + b1;
                    if (RELU) { f0 = fmaxf(f0, 0.f); f1 = fmaxf(f1, 0.f); }
                    const size_t grow = (size_t)(off + m0 + r);
                    if (ATOMIC_OUT) {
                        const int   t = g_tok[grow];
                        const float w = g_rw[grow];
                        float* op = Cf + (size_t)t * N + n0 + c;
                        atomicAdd(op,     w * f0);
                        atomicAdd(op + 1, w * f1);
                    } else {
                        const size_t o = grow * N + n0 + c;
                        __half2 hp = {__float2half_rn(f0), __float2half_rn(f1)};
                        *reinterpret_cast<__half2*>(Ch + o) = hp;
                    }
                }
            }
        }
}

// ---------------- launch ----------------
extern "C" void kernel_launch(void* const* d_in, const int* in_sizes, int n_in,
                              void* d_out, int out_size) {
    const float* x  = (const float*)d_in[0];
    const float* Wg = (const float*)d_in[1];
    const float* W1 = (const float*)d_in[2];
    const float* b1 = (const float*)d_in[3];
    const float* W2 = (const float*)d_in[4];
    const float* b2 = (const float*)d_in[5];
    float* out = (float*)d_out;

    const int T = in_sizes[0] / D_MODEL;   // 4096

    __half *x16, *w1, *w2, *h16;
    cudaGetSymbolAddress((void**)&x16, g_x16);
    cudaGetSymbolAddress((void**)&w1,  g_w1);
    cudaGetSymbolAddress((void**)&w2,  g_w2);
    cudaGetSymbolAddress((void**)&h16, g_h16);

    cudaFuncSetAttribute(mma_gemm<1, true, true, false, true>,
                         cudaFuncAttributeMaxDynamicSharedMemorySize, SMEM_SZ);
    cudaFuncSetAttribute(mma_gemm<1, false, false, true, false>,
                         cudaFuncAttributeMaxDynamicSharedMemorySize, SMEM_SZ);

    size_t nw = (size_t)N_EXP * D_MODEL * D_FF;

    front_kernel<<<FRONT_CTAS, 256>>>(x, Wg, out, T, W1, w1, nw, x16);
    route_kernel<<<1, 256>>>(T);

    // GEMM1: h = relu(x @ W1 + b1), fp16 out. x==last CTAs convert W2 (interleaved).
    mma_gemm<1, true, true, false, true>
        <<<dim3(D_FF / 128 + 1, MAX_T / 128, N_EXP), 256, SMEM_SZ>>>(
        x16, w1, b1, nullptr, h16, D_MODEL, D_FF, W2, w2, nw);
    // GEMM2: atomic weighted-scatter into out (combine fused)
    mma_gemm<1, false, false, true, false>
        <<<dim3(D_MODEL / 128, MAX_T / 128, N_EXP), 256, SMEM_SZ>>>(
        h16, w2, b2, out, nullptr, D_FF, D_MODEL, nullptr, nullptr, 0);
}